// round 1
// baseline (speedup 1.0000x reference)
#include <cuda_runtime.h>

#define BATCH 4
#define SEQ   4096
#define HID   256
#define MTOT  (BATCH * SEQ)

// Scratch for projected Q, K, V (16 MB each). Q is pre-scaled by 1/sqrt(H) at
// attention load time instead (cheaper: folded into smem fill).
__device__ float g_Q[MTOT * HID];
__device__ float g_K[MTOT * HID];
__device__ float g_V[MTOT * HID];

// ---------------------------------------------------------------------------
// Kernel 1: fused QKV projection.
// Out[m][n] = sum_k X[m][k] * W[k][n];  M=16384, N=256, K=256.
// blockIdx.z selects {Q, K, V}. BM=64, BN=64, BK=32, 256 threads, 4x4/thread.
// ---------------------------------------------------------------------------
__global__ __launch_bounds__(256) void qkv_gemm(
    const float* __restrict__ X,
    const float* __restrict__ Wq,
    const float* __restrict__ Wk,
    const float* __restrict__ Wv)
{
    __shared__ float As[64][33];   // padded: broadcast-friendly reads
    __shared__ float Bs[32][64];

    const float* W;
    float* O;
    if (blockIdx.z == 0)      { W = Wq; O = g_Q; }
    else if (blockIdx.z == 1) { W = Wk; O = g_K; }
    else                      { W = Wv; O = g_V; }

    const int bm = blockIdx.x * 64;
    const int bn = blockIdx.y * 64;
    const int t  = threadIdx.x;
    const int tx = t & 15;
    const int ty = t >> 4;

    float acc[4][4] = {};

    for (int k0 = 0; k0 < HID; k0 += 32) {
        // Load A tile 64x32 (512 float4, 2 per thread), coalesced.
        #pragma unroll
        for (int e = 0; e < 2; e++) {
            int f  = e * 256 + t;
            int m  = f >> 3;
            int k4 = f & 7;
            float4 v = *reinterpret_cast<const float4*>(X + (size_t)(bm + m) * HID + k0 + k4 * 4);
            As[m][k4 * 4 + 0] = v.x;
            As[m][k4 * 4 + 1] = v.y;
            As[m][k4 * 4 + 2] = v.z;
            As[m][k4 * 4 + 3] = v.w;
        }
        // Load B tile 32x64 (512 float4, 2 per thread), coalesced.
        #pragma unroll
        for (int e = 0; e < 2; e++) {
            int f  = e * 256 + t;
            int k  = f >> 4;
            int n4 = f & 15;
            float4 v = *reinterpret_cast<const float4*>(W + (size_t)(k0 + k) * HID + bn + n4 * 4);
            *reinterpret_cast<float4*>(&Bs[k][n4 * 4]) = v;
        }
        __syncthreads();

        #pragma unroll
        for (int kk = 0; kk < 32; kk++) {
            float a0 = As[ty * 4 + 0][kk];
            float a1 = As[ty * 4 + 1][kk];
            float a2 = As[ty * 4 + 2][kk];
            float a3 = As[ty * 4 + 3][kk];
            float4 bb = *reinterpret_cast<const float4*>(&Bs[kk][tx * 4]);
            acc[0][0] += a0 * bb.x; acc[0][1] += a0 * bb.y; acc[0][2] += a0 * bb.z; acc[0][3] += a0 * bb.w;
            acc[1][0] += a1 * bb.x; acc[1][1] += a1 * bb.y; acc[1][2] += a1 * bb.z; acc[1][3] += a1 * bb.w;
            acc[2][0] += a2 * bb.x; acc[2][1] += a2 * bb.y; acc[2][2] += a2 * bb.z; acc[2][3] += a2 * bb.w;
            acc[3][0] += a3 * bb.x; acc[3][1] += a3 * bb.y; acc[3][2] += a3 * bb.z; acc[3][3] += a3 * bb.w;
        }
        __syncthreads();
    }

    #pragma unroll
    for (int r = 0; r < 4; r++) {
        float4 v;
        v.x = acc[r][0]; v.y = acc[r][1]; v.z = acc[r][2]; v.w = acc[r][3];
        *reinterpret_cast<float4*>(O + (size_t)(bm + ty * 4 + r) * HID + bn + tx * 4) = v;
    }
}

// ---------------------------------------------------------------------------
// Kernel 2: flash-attention (fp32, online softmax).
// One CTA per (batch, 64-query tile). 256 threads.
// Thread t: row i = t&63, column-group jc = t>>6 (16 score cols / 64 out dims).
// ---------------------------------------------------------------------------
#define QS_STRIDE 260                 // 256 + 4 pad (keeps 16B alignment)
#define PS_STRIDE 65                  // odd stride -> conflict-free row reads
#define SMEM_F (64 * QS_STRIDE + 2 * 64 * 256 + 64 * PS_STRIDE + 2 * 256)
#define SMEM_BYTES (SMEM_F * 4)

__global__ __launch_bounds__(256, 1) void attn(float* __restrict__ out)
{
    extern __shared__ float sm[];
    float* Qs = sm;                          // 64 x QS_STRIDE (pre-scaled Q)
    float* Ks = Qs + 64 * QS_STRIDE;         // 64 x 256
    float* Vs = Ks + 64 * 256;               // 64 x 256
    float* Ps = Vs + 64 * 256;               // 64 x PS_STRIDE
    float* Rm = Ps + 64 * PS_STRIDE;         // 64 x 4 (rowmax partials)
    float* Rs = Rm + 256;                    // 64 x 4 (rowsum partials)

    const int b  = blockIdx.y;
    const int q0 = blockIdx.x * 64;
    const int t  = threadIdx.x;
    const float scale = 0.0625f;             // 1/sqrt(256)

    // Load + scale Q tile (64x256), coalesced float4.
    const float* Qg = g_Q + ((size_t)b * SEQ + q0) * HID;
    #pragma unroll
    for (int e = 0; e < 16; e++) {
        int f  = e * 256 + t;
        int i  = f >> 6;
        int d4 = f & 63;
        float4 v = *reinterpret_cast<const float4*>(Qg + (size_t)i * HID + d4 * 4);
        v.x *= scale; v.y *= scale; v.z *= scale; v.w *= scale;
        *reinterpret_cast<float4*>(Qs + i * QS_STRIDE + d4 * 4) = v;
    }

    const int i  = t & 63;     // my query row within tile
    const int jc = t >> 6;     // 0..3
    const int cb = jc * 64;    // my output-dim chunk base

    float m_old = -1e30f;
    float l = 0.0f;
    float4 O4[16];
    #pragma unroll
    for (int e = 0; e < 16; e++) O4[e] = make_float4(0.f, 0.f, 0.f, 0.f);

    const float* Kg = g_K + (size_t)b * SEQ * HID;
    const float* Vg = g_V + (size_t)b * SEQ * HID;

    for (int kt = 0; kt < SEQ / 64; kt++) {
        __syncthreads();   // previous iteration's Vs/Ps reads done
        const float* Ktile = Kg + (size_t)kt * 64 * HID;
        const float* Vtile = Vg + (size_t)kt * 64 * HID;
        #pragma unroll
        for (int e = 0; e < 16; e++) {
            int f  = e * 256 + t;
            int r  = f >> 6;
            int d4 = f & 63;
            *reinterpret_cast<float4*>(Ks + r * 256 + d4 * 4) =
                *reinterpret_cast<const float4*>(Ktile + (size_t)r * HID + d4 * 4);
            *reinterpret_cast<float4*>(Vs + r * 256 + d4 * 4) =
                *reinterpret_cast<const float4*>(Vtile + (size_t)r * HID + d4 * 4);
        }
        __syncthreads();

        // S[i][jc*16+jj] = Qs[i] . Ks[j]   (Q pre-scaled)
        float s[16];
        #pragma unroll
        for (int jj = 0; jj < 16; jj++) s[jj] = 0.f;

        const float4* Qr = reinterpret_cast<const float4*>(Qs + i * QS_STRIDE);
        for (int d4 = 0; d4 < 64; d4++) {
            float4 a = Qr[d4];
            #pragma unroll
            for (int jj = 0; jj < 16; jj++) {
                float4 bv = *reinterpret_cast<const float4*>(Ks + (jc * 16 + jj) * 256 + d4 * 4);
                s[jj] += a.x * bv.x + a.y * bv.y + a.z * bv.z + a.w * bv.w;
            }
        }

        // Online softmax: row max across 4 thread-groups
        float lm = s[0];
        #pragma unroll
        for (int jj = 1; jj < 16; jj++) lm = fmaxf(lm, s[jj]);
        Rm[i * 4 + jc] = lm;
        __syncthreads();
        float rmax = fmaxf(fmaxf(Rm[i * 4 + 0], Rm[i * 4 + 1]),
                           fmaxf(Rm[i * 4 + 2], Rm[i * 4 + 3]));
        float m_new = fmaxf(m_old, rmax);
        float alpha = __expf(m_old - m_new);

        float ls = 0.f;
        #pragma unroll
        for (int jj = 0; jj < 16; jj++) {
            float p = __expf(s[jj] - m_new);
            ls += p;
            Ps[i * PS_STRIDE + jc * 16 + jj] = p;
        }
        Rs[i * 4 + jc] = ls;
        __syncthreads();
        l = l * alpha + (Rs[i * 4 + 0] + Rs[i * 4 + 1] + Rs[i * 4 + 2] + Rs[i * 4 + 3]);
        m_old = m_new;

        // Rescale accumulator, then O += P . V
        #pragma unroll
        for (int e = 0; e < 16; e++) {
            O4[e].x *= alpha; O4[e].y *= alpha; O4[e].z *= alpha; O4[e].w *= alpha;
        }
        for (int j = 0; j < 64; j++) {
            float p = Ps[i * PS_STRIDE + j];
            const float4* Vr = reinterpret_cast<const float4*>(Vs + j * 256 + cb);
            #pragma unroll
            for (int e = 0; e < 16; e++) {
                float4 v = Vr[e];
                O4[e].x += p * v.x; O4[e].y += p * v.y;
                O4[e].z += p * v.z; O4[e].w += p * v.w;
            }
        }
    }

    // Normalize and write out[b][q0+i][cb..cb+63]
    float inv = 1.0f / l;
    float* og = out + (((size_t)b * SEQ) + q0 + i) * HID + cb;
    #pragma unroll
    for (int e = 0; e < 16; e++) {
        float4 v = O4[e];
        v.x *= inv; v.y *= inv; v.z *= inv; v.w *= inv;
        *reinterpret_cast<float4*>(og + e * 4) = v;
    }
}

// ---------------------------------------------------------------------------
extern "C" void kernel_launch(void* const* d_in, const int* in_sizes, int n_in,
                              void* d_out, int out_size)
{
    const float* X  = (const float*)d_in[0];
    const float* Wq = (const float*)d_in[1];
    const float* Wk = (const float*)d_in[2];
    const float* Wv = (const float*)d_in[3];
    // d_in[4] = lengths (int64) — unused by the reference module.
    float* out = (float*)d_out;

    cudaFuncSetAttribute(attn, cudaFuncAttributeMaxDynamicSharedMemorySize, SMEM_BYTES);

    qkv_gemm<<<dim3(MTOT / 64, HID / 64, 3), 256>>>(X, Wq, Wk, Wv);
    attn<<<dim3(SEQ / 64, BATCH), 256, SMEM_BYTES>>>(out);
}